// round 15
// baseline (speedup 1.0000x reference)
#include <cuda_runtime.h>
#include <cstdint>
#include <cstddef>

// ---------------------------------------------------------------------------
// Scratch (device globals — no allocation allowed)
// ---------------------------------------------------------------------------
__device__ float g_noise[(size_t)1024 * 131072];   // 512 MiB prescaled gumbel noise
__device__ float g_h1[64 * 8192];
__device__ float g_h2[64 * 8192];
__device__ float g_mask0[64 * 2048];
__device__ float g_p [(size_t)8 * 64 * 8192];      // K-split partials (g1 x4 / g2 x8)
__device__ float g_p3[(size_t)16 * 64 * 2048];     // gemm3 x16 partials
__device__ uint2 g_keys[1024];

// ---------------------------------------------------------------------------
// Threefry-2x32-20 (bit-exact JAX)
// ---------------------------------------------------------------------------
__device__ __forceinline__ void tf_block(uint32_t ks0, uint32_t ks1, uint32_t ks2,
                                         uint32_t x0, uint32_t x1,
                                         uint32_t& o0, uint32_t& o1)
{
    x0 += ks0; x1 += ks1;
#define TFR(r) { x0 += x1; x1 = __funnelshift_l(x1, x1, (r)); x1 ^= x0; }
    TFR(13); TFR(15); TFR(26); TFR(6);
    x0 += ks1; x1 += ks2 + 1u;
    TFR(17); TFR(29); TFR(16); TFR(24);
    x0 += ks2; x1 += ks0 + 2u;
    TFR(13); TFR(15); TFR(26); TFR(6);
    x0 += ks0; x1 += ks1 + 3u;
    TFR(17); TFR(29); TFR(16); TFR(24);
    x0 += ks1; x1 += ks2 + 4u;
    TFR(13); TFR(15); TFR(26); TFR(6);
    x0 += ks2; x1 += ks0 + 5u;
#undef TFR
    o0 = x0; o1 = x1;
}

// per-replay init: fold per-iteration keys
__global__ void keys_kernel()
{
    int i = threadIdx.x;
    uint32_t o0, o1;
    tf_block(0u, 42u, 0u ^ 42u ^ 0x1BD11BDAu, 0u, (uint32_t)i, o0, o1);
    g_keys[i] = make_uint2(o0, o1);
}

// bits -> n = -2*log2(-ln u)  so the iter loop is e = 2^(mask*C + n), C = 2*log2(e)
__device__ __forceinline__ float bits_to_noise(uint32_t bits)
{
    const uint32_t mant = bits >> 9;
    const float fl = __uint_as_float(0x3F800000u | mant) - 1.0f;  // exact m*2^-23
    float L;
    const float d = 1.0f - fl;
    if (d <= 0.015625f) {
        L = d * (1.0f + d * (0.5f + d * (0.3333333432674408f + d * 0.25f)));
    } else if (mant == 0u) {
        L = 87.336544750553109f;                                  // -ln(2^-126)
    } else {
        L = -0.69314718055994531f * __log2f(fl);
    }
    return -2.0f * __log2f(L);
}

// ---------------------------------------------------------------------------
// Noise warp-job: one warp generates 512 elements (16/thread).
// Global job g: iteration i = g>>8, chunk c = g&255. 262144 jobs total.
// No block syncs — warps are fully independent.
// ---------------------------------------------------------------------------
__device__ __forceinline__ void noise_jobs(int jobBase, int njobs)
{
    const int lane = threadIdx.x & 31;
    for (int q = 0; q < njobs; q++) {
        const int g = jobBase + q;
        const int i = g >> 8;
        const int c = g & 255;
        const uint2 key = g_keys[i];
        const uint32_t k1 = key.x, k2 = key.y;
        const uint32_t ks2 = k1 ^ k2 ^ 0x1BD11BDAu;
        float* out = g_noise + (size_t)i * 131072u + (uint32_t)c * 512u + lane;
        const uint32_t j0 = (uint32_t)c * 512u + lane;
#pragma unroll 8
        for (int t = 0; t < 16; t++) {
            uint32_t o0, o1;
            tf_block(k1, k2, ks2, 0u, j0 + (uint32_t)t * 32u, o0, o1);
            out[t * 32] = bits_to_noise(o0 ^ o1);
        }
    }
}

// ---------------------------------------------------------------------------
// Hybrid CTA: 512 threads. Warps 0-7 = noise (low wid -> low arbiter prio);
// warps 8-15 = gemm (high wid -> issue priority). Gemm uses named barrier 1.
// Gemm: 64 x N fp32, 64x64 tile, 8 warps, 4x4/thread scalar FFMA (pure fma
// pipe), double-buffered smem, K-split -> raw partials P[kc][64][N].
// ---------------------------------------------------------------------------
#define GBAR() asm volatile("bar.sync 1, 256;" ::: "memory")

template <int COLTILES, int KSPLIT, int JPW>
__global__ __launch_bounds__(512) void gemm_noise(const float* __restrict__ X,
                                                  const float* __restrict__ W,
                                                  float* __restrict__ P,
                                                  int K, int N, int jobBase)
{
    __shared__ __align__(16) float Xs[2][1024];   // [kk][m]
    __shared__ __align__(16) float Ws[2][1024];   // [kk][n]

    const int tid = threadIdx.x;
    const int wid = tid >> 5;

    if (wid < 8) {   // ---- noise role ----
        noise_jobs(jobBase + ((int)blockIdx.x * 8 + wid) * JPW, JPW);
        return;
    }

    // ---- gemm role (256 threads, t2 in [0,256)) ----
    const int t2 = tid - 256;
    const int tx = t2 & 15, ty = t2 >> 4;
    const int col = blockIdx.x % COLTILES;
    const int kc  = blockIdx.x / COLTILES;
    const int cb  = col * 64;
    const int Kc  = K / KSPLIT;
    const int k0  = kc * Kc;

    const int lm = t2 >> 2;
    const int lk = (t2 & 3) << 2;
    const int wk = t2 >> 4;
    const int wn = (t2 & 15) << 2;

    float acc[4][4] = {};

    float4 xa = *reinterpret_cast<const float4*>(X + (size_t)lm * K + k0 + lk);
    float4 wa = *reinterpret_cast<const float4*>(W + (size_t)(k0 + wk) * N + cb + wn);
    Xs[0][(lk + 0) * 64 + lm] = xa.x;
    Xs[0][(lk + 1) * 64 + lm] = xa.y;
    Xs[0][(lk + 2) * 64 + lm] = xa.z;
    Xs[0][(lk + 3) * 64 + lm] = xa.w;
    *reinterpret_cast<float4*>(&Ws[0][wk * 64 + wn]) = wa;
    GBAR();

    const int nt = Kc >> 4;
    int buf = 0;
    for (int t = 0; t < nt; t++) {
        float4 xn, wn4;
        const bool more = (t + 1 < nt);
        if (more) {
            int kk0 = k0 + ((t + 1) << 4);
            xn  = *reinterpret_cast<const float4*>(X + (size_t)lm * K + kk0 + lk);
            wn4 = *reinterpret_cast<const float4*>(W + (size_t)(kk0 + wk) * N + cb + wn);
        }
#pragma unroll
        for (int kk = 0; kk < 16; kk++) {
            const float4 a4 = *reinterpret_cast<const float4*>(&Xs[buf][(kk << 6) + (ty << 2)]);
            const float4 b4 = *reinterpret_cast<const float4*>(&Ws[buf][(kk << 6) + (tx << 2)]);
            const float av[4] = {a4.x, a4.y, a4.z, a4.w};
            const float bv[4] = {b4.x, b4.y, b4.z, b4.w};
#pragma unroll
            for (int i2 = 0; i2 < 4; i2++)
#pragma unroll
                for (int j2 = 0; j2 < 4; j2++)
                    acc[i2][j2] = fmaf(av[i2], bv[j2], acc[i2][j2]);
        }
        if (more) {
            const int nb = buf ^ 1;
            Xs[nb][(lk + 0) * 64 + lm] = xn.x;
            Xs[nb][(lk + 1) * 64 + lm] = xn.y;
            Xs[nb][(lk + 2) * 64 + lm] = xn.z;
            Xs[nb][(lk + 3) * 64 + lm] = xn.w;
            *reinterpret_cast<float4*>(&Ws[nb][wk * 64 + wn]) = wn4;
            buf = nb;
        }
        GBAR();
    }

    float* dst = P + (size_t)kc * 64 * N;
#pragma unroll
    for (int i = 0; i < 4; i++) {
        float4 o = make_float4(acc[i][0], acc[i][1], acc[i][2], acc[i][3]);
        *reinterpret_cast<float4*>(dst + (size_t)((ty << 2) + i) * N + cb + (tx << 2)) = o;
    }
}

// ---------------------------------------------------------------------------
// K-split reduce + bias + batch-BN (+ affine + ReLU). Small noise remainder
// rides on extra CTAs (256 thr, 8 warps x JPW jobs each).
// ---------------------------------------------------------------------------
template <bool AR, int S, int RED, int JPW>
__global__ __launch_bounds__(256) void reduce_noise(const float* __restrict__ P,
                                                    const float* __restrict__ bias,
                                                    const float* __restrict__ gamma,
                                                    const float* __restrict__ beta,
                                                    float* __restrict__ Y, int N,
                                                    int jobBase)
{
    if (blockIdx.x >= RED) {
        const int b = (int)blockIdx.x - RED;
        const int wid = threadIdx.x >> 5;
        noise_jobs(jobBase + (b * 8 + wid) * JPW, JPW);
        return;
    }

    const int c = blockIdx.x * 256 + threadIdx.x;
    const float b = bias[c];
    float s = 0.f, ss = 0.f;
#pragma unroll 4
    for (int r = 0; r < 64; r++) {
        float v = b;
#pragma unroll
        for (int q = 0; q < S; q++) v += P[((size_t)q * 64 + r) * N + c];
        s += v; ss += v * v;
    }
    const float mean = s * 0.015625f;
    const float inv  = rsqrtf(fmaf(-mean, mean, ss * 0.015625f) + 1e-5f);
    const float ga = AR ? gamma[c] : 1.0f;
    const float be = AR ? beta[c]  : 0.0f;
#pragma unroll 4
    for (int r = 0; r < 64; r++) {
        float v = b;
#pragma unroll
        for (int q = 0; q < S; q++) v += P[((size_t)q * 64 + r) * N + c];
        float y = (v - mean) * inv;
        if (AR) y = fmaxf(fmaf(y, ga, be), 0.0f);
        Y[(size_t)r * N + c] = y;
    }
}

// ---------------------------------------------------------------------------
// Iteration kernel: pure (all noise complete). 64 CTAs, 256 thr, 8 cols/thr.
// Depth-3 software pipeline covers DRAM latency on the noise stream.
// ---------------------------------------------------------------------------
__device__ __forceinline__ float ex2f(float x)
{
    float y; asm("ex2.approx.f32 %0, %1;" : "=f"(y) : "f"(x)); return y;
}

__global__ __launch_bounds__(256) void iter_k(float* __restrict__ zout)
{
    const int row  = blockIdx.x;
    const int tid  = threadIdx.x;
    const int lane = tid & 31, wid = tid >> 5;
    const float C = 2.8853900817779268f;   // 2*log2(e)

    float4 ma = *(const float4*)(g_mask0 + row * 2048 + 8 * tid);
    float4 mb = *(const float4*)(g_mask0 + row * 2048 + 8 * tid + 4);
    float4 za = make_float4(0.f, 0.f, 0.f, 0.f);
    float4 zb = make_float4(0.f, 0.f, 0.f, 0.f);

    __shared__ __align__(16) float wsum[2][8];

    const float4* np = (const float4*)g_noise + (size_t)row * 512 + 2 * tid;

    float4 a0 = np[0],                   b0 = np[1];
    float4 a1 = np[(size_t)1 * 32768],   b1 = np[(size_t)1 * 32768 + 1];
    float4 a2 = np[(size_t)2 * 32768],   b2 = np[(size_t)2 * 32768 + 1];

    for (int i = 0; i < 1024; i++) {
        const float e0 = ex2f(fmaf(ma.x, C, a0.x));
        const float e1 = ex2f(fmaf(ma.y, C, a0.y));
        const float e2 = ex2f(fmaf(ma.z, C, a0.z));
        const float e3 = ex2f(fmaf(ma.w, C, a0.w));
        const float e4 = ex2f(fmaf(mb.x, C, b0.x));
        const float e5 = ex2f(fmaf(mb.y, C, b0.y));
        const float e6 = ex2f(fmaf(mb.z, C, b0.z));
        const float e7 = ex2f(fmaf(mb.w, C, b0.w));

        a0 = a1; b0 = b1;
        a1 = a2; b1 = b2;
        if (i + 3 < 1024) {
            a2 = np[(size_t)(i + 3) * 32768];
            b2 = np[(size_t)(i + 3) * 32768 + 1];
        }

        float s = ((e0 + e1) + (e2 + e3)) + ((e4 + e5) + (e6 + e7));
#pragma unroll
        for (int o = 16; o; o >>= 1) s += __shfl_xor_sync(0xffffffffu, s, o);
        if (lane == 0) wsum[i & 1][wid] = s;
        __syncthreads();

        const float4* wp = (const float4*)wsum[i & 1];
        const float4 t0 = wp[0], t1 = wp[1];
        const float tt = ((t0.x + t0.y) + (t0.z + t0.w)) + ((t1.x + t1.y) + (t1.z + t1.w));
        float r; asm("rcp.approx.f32 %0, %1;" : "=f"(r) : "f"(tt));
        ma.x = e0 * r; ma.y = e1 * r; ma.z = e2 * r; ma.w = e3 * r;
        mb.x = e4 * r; mb.y = e5 * r; mb.z = e6 * r; mb.w = e7 * r;
        za.x = fmaxf(za.x, ma.x); za.y = fmaxf(za.y, ma.y);
        za.z = fmaxf(za.z, ma.z); za.w = fmaxf(za.w, ma.w);
        zb.x = fmaxf(zb.x, mb.x); zb.y = fmaxf(zb.y, mb.y);
        zb.z = fmaxf(zb.z, mb.z); zb.w = fmaxf(zb.w, mb.w);
    }
    *(float4*)(zout + row * 2048 + 8 * tid)     = za;
    *(float4*)(zout + row * 2048 + 8 * tid + 4) = zb;
}

// ---------------------------------------------------------------------------
// Launch. Job budget (512-elem warp-jobs), 262144 total — packed into the
// hybrid gemm launches (both pipes saturated); small remainders on reduces:
//   g1: 512 CTAs x 8 x 10 =  40960 @0
//   r1: 256 noise CTAs x 8 x 4 = 8192 @40960
//   g2: 1024 x 8 x 18     = 147456 @49152
//   r2: 128 x 8 x 4       =   4096 @196608
//   g3: 512 x 8 x 14      =  57344 @200704
//   r3: 128 x 8 x 4       =   4096 @258048     (sum = 262144)
// ---------------------------------------------------------------------------
extern "C" void kernel_launch(void* const* d_in, const int* in_sizes, int n_in,
                              void* d_out, int out_size)
{
    const float* f   = (const float*)d_in[0];
    const float* W1  = (const float*)d_in[1];
    const float* b1  = (const float*)d_in[2];
    const float* g1  = (const float*)d_in[3];
    const float* be1 = (const float*)d_in[4];
    const float* W2  = (const float*)d_in[5];
    const float* b2  = (const float*)d_in[6];
    const float* g2  = (const float*)d_in[7];
    const float* be2 = (const float*)d_in[8];
    const float* W3  = (const float*)d_in[9];
    const float* b3  = (const float*)d_in[10];
    float* out = (float*)d_out;

    void *p1, *p2, *p3, *pp, *pp3;
    cudaGetSymbolAddress(&p1, g_h1);
    cudaGetSymbolAddress(&p2, g_h2);
    cudaGetSymbolAddress(&p3, g_mask0);
    cudaGetSymbolAddress(&pp, g_p);
    cudaGetSymbolAddress(&pp3, g_p3);
    float* h1 = (float*)p1;
    float* h2 = (float*)p2;
    float* mk = (float*)p3;
    float* P  = (float*)pp;
    float* P3 = (float*)pp3;

    keys_kernel<<<1, 1024>>>();

    gemm_noise<128, 4, 10><<<512, 512>>>(f,  W1, P, 2048, 8192, 0);
    reduce_noise<true, 4, 32, 4><<<32 + 256, 256>>>(P, b1, g1, be1, h1, 8192, 40960);

    gemm_noise<128, 8, 18><<<1024, 512>>>(h1, W2, P, 8192, 8192, 49152);
    reduce_noise<true, 8, 32, 4><<<32 + 128, 256>>>(P, b2, g2, be2, h2, 8192, 196608);

    gemm_noise<32, 16, 14><<<512, 512>>>(h2, W3, P3, 8192, 2048, 200704);
    reduce_noise<false, 16, 8, 4><<<8 + 128, 256>>>(P3, b3, nullptr, nullptr, mk, 2048, 258048);

    iter_k<<<64, 256>>>(out);
}

// round 16
// speedup vs baseline: 1.1055x; 1.1055x over previous
#include <cuda_runtime.h>
#include <cstdint>
#include <cstddef>

// ---------------------------------------------------------------------------
// Scratch (device globals — no allocation allowed)
// ---------------------------------------------------------------------------
__device__ float g_noise[(size_t)1024 * 131072];   // 512 MiB prescaled gumbel noise
__device__ float g_h1[64 * 8192];
__device__ float g_h2[64 * 8192];
__device__ float g_mask0[64 * 2048];
__device__ float g_p [(size_t)8 * 64 * 8192];      // K-split partials (g1 x4 / g2 x8)
__device__ float g_p3[(size_t)8 * 64 * 2048];      // gemm3 x8 partials
__device__ uint2 g_keys[1024];

#define PGRID 296   // persistent hybrid grid: 2 CTAs/SM x 148 SMs, one wave

// ---------------------------------------------------------------------------
// Threefry-2x32-20 (bit-exact JAX)
// ---------------------------------------------------------------------------
__device__ __forceinline__ void tf_block(uint32_t ks0, uint32_t ks1, uint32_t ks2,
                                         uint32_t x0, uint32_t x1,
                                         uint32_t& o0, uint32_t& o1)
{
    x0 += ks0; x1 += ks1;
#define TFR(r) { x0 += x1; x1 = __funnelshift_l(x1, x1, (r)); x1 ^= x0; }
    TFR(13); TFR(15); TFR(26); TFR(6);
    x0 += ks1; x1 += ks2 + 1u;
    TFR(17); TFR(29); TFR(16); TFR(24);
    x0 += ks2; x1 += ks0 + 2u;
    TFR(13); TFR(15); TFR(26); TFR(6);
    x0 += ks0; x1 += ks1 + 3u;
    TFR(17); TFR(29); TFR(16); TFR(24);
    x0 += ks1; x1 += ks2 + 4u;
    TFR(13); TFR(15); TFR(26); TFR(6);
    x0 += ks2; x1 += ks0 + 5u;
#undef TFR
    o0 = x0; o1 = x1;
}

// per-replay init: fold per-iteration keys
__global__ void keys_kernel()
{
    int i = threadIdx.x;
    uint32_t o0, o1;
    tf_block(0u, 42u, 0u ^ 42u ^ 0x1BD11BDAu, 0u, (uint32_t)i, o0, o1);
    g_keys[i] = make_uint2(o0, o1);
}

// bits -> n = -2*log2(-ln u)  so the iter loop is e = 2^(mask*C + n), C = 2*log2(e)
__device__ __forceinline__ float bits_to_noise(uint32_t bits)
{
    const uint32_t mant = bits >> 9;
    const float fl = __uint_as_float(0x3F800000u | mant) - 1.0f;  // exact m*2^-23
    float L;
    const float d = 1.0f - fl;
    if (d <= 0.015625f) {
        L = d * (1.0f + d * (0.5f + d * (0.3333333432674408f + d * 0.25f)));
    } else if (mant == 0u) {
        L = 87.336544750553109f;                                  // -ln(2^-126)
    } else {
        L = -0.69314718055994531f * __log2f(fl);
    }
    return -2.0f * __log2f(L);
}

// ---------------------------------------------------------------------------
// Noise warp-job: one warp generates 512 elements (16/thread).
// Global job g: iteration i = g>>8, chunk c = g&255. 262144 jobs total.
// No block syncs — warps are fully independent.
// ---------------------------------------------------------------------------
__device__ __forceinline__ void noise_jobs(int jobBase, int njobs)
{
    const int lane = threadIdx.x & 31;
    for (int q = 0; q < njobs; q++) {
        const int g = jobBase + q;
        const int i = g >> 8;
        const int c = g & 255;
        const uint2 key = g_keys[i];
        const uint32_t k1 = key.x, k2 = key.y;
        const uint32_t ks2 = k1 ^ k2 ^ 0x1BD11BDAu;
        float* out = g_noise + (size_t)i * 131072u + (uint32_t)c * 512u + lane;
        const uint32_t j0 = (uint32_t)c * 512u + lane;
#pragma unroll 8
        for (int t = 0; t < 16; t++) {
            uint32_t o0, o1;
            tf_block(k1, k2, ks2, 0u, j0 + (uint32_t)t * 32u, o0, o1);
            out[t * 32] = bits_to_noise(o0 ^ o1);
        }
    }
}

// ---------------------------------------------------------------------------
// Persistent hybrid CTA: 512 threads, grid = PGRID (one wave, 2 CTAs/SM).
// Warps 0-7 = noise; warps 8-15 = gemm (hi wid -> arbiter priority).
// Gemm warps loop over tiles (stride PGRID) -> no wave quantization; ragged
// tile counts are absorbed warp-locally by the co-resident noise warps.
// Gemm: 64 x N fp32, 64x64 tile, 4x4/thread scalar FFMA (pure fma pipe),
// double-buffered smem, K-split -> raw partials P[kc][64][N].
// ---------------------------------------------------------------------------
#define GBAR() asm volatile("bar.sync 1, 256;" ::: "memory")

template <int COLTILES, int KSPLIT, int JPW>
__global__ __launch_bounds__(512) void gemm_noise(const float* __restrict__ X,
                                                  const float* __restrict__ W,
                                                  float* __restrict__ P,
                                                  int K, int N, int jobBase)
{
    constexpr int NTILES = COLTILES * KSPLIT;

    __shared__ __align__(16) float Xs[2][1024];   // [kk][m]
    __shared__ __align__(16) float Ws[2][1024];   // [kk][n]

    const int tid = threadIdx.x;
    const int wid = tid >> 5;

    if (wid < 8) {   // ---- noise role ----
        noise_jobs(jobBase + ((int)blockIdx.x * 8 + wid) * JPW, JPW);
        return;
    }

    // ---- gemm role (256 threads, t2 in [0,256)) ----
    const int t2 = tid - 256;
    const int tx = t2 & 15, ty = t2 >> 4;
    const int Kc = K / KSPLIT;

    const int lm = t2 >> 2;
    const int lk = (t2 & 3) << 2;
    const int wk = t2 >> 4;
    const int wn = (t2 & 15) << 2;

    for (int tile = (int)blockIdx.x; tile < NTILES; tile += PGRID) {
        const int col = tile % COLTILES;
        const int kc  = tile / COLTILES;
        const int cb  = col * 64;
        const int k0  = kc * Kc;

        float acc[4][4] = {};

        float4 xa = *reinterpret_cast<const float4*>(X + (size_t)lm * K + k0 + lk);
        float4 wa = *reinterpret_cast<const float4*>(W + (size_t)(k0 + wk) * N + cb + wn);
        Xs[0][(lk + 0) * 64 + lm] = xa.x;
        Xs[0][(lk + 1) * 64 + lm] = xa.y;
        Xs[0][(lk + 2) * 64 + lm] = xa.z;
        Xs[0][(lk + 3) * 64 + lm] = xa.w;
        *reinterpret_cast<float4*>(&Ws[0][wk * 64 + wn]) = wa;
        GBAR();

        const int nt = Kc >> 4;
        int buf = 0;
        for (int t = 0; t < nt; t++) {
            float4 xn, wn4;
            const bool more = (t + 1 < nt);
            if (more) {
                int kk0 = k0 + ((t + 1) << 4);
                xn  = *reinterpret_cast<const float4*>(X + (size_t)lm * K + kk0 + lk);
                wn4 = *reinterpret_cast<const float4*>(W + (size_t)(kk0 + wk) * N + cb + wn);
            }
#pragma unroll
            for (int kk = 0; kk < 16; kk++) {
                const float4 a4 = *reinterpret_cast<const float4*>(&Xs[buf][(kk << 6) + (ty << 2)]);
                const float4 b4 = *reinterpret_cast<const float4*>(&Ws[buf][(kk << 6) + (tx << 2)]);
                const float av[4] = {a4.x, a4.y, a4.z, a4.w};
                const float bv[4] = {b4.x, b4.y, b4.z, b4.w};
#pragma unroll
                for (int i2 = 0; i2 < 4; i2++)
#pragma unroll
                    for (int j2 = 0; j2 < 4; j2++)
                        acc[i2][j2] = fmaf(av[i2], bv[j2], acc[i2][j2]);
            }
            if (more) {
                const int nb = buf ^ 1;
                Xs[nb][(lk + 0) * 64 + lm] = xn.x;
                Xs[nb][(lk + 1) * 64 + lm] = xn.y;
                Xs[nb][(lk + 2) * 64 + lm] = xn.z;
                Xs[nb][(lk + 3) * 64 + lm] = xn.w;
                *reinterpret_cast<float4*>(&Ws[nb][wk * 64 + wn]) = wn4;
                buf = nb;
            }
            GBAR();
        }

        float* dst = P + (size_t)kc * 64 * N;
#pragma unroll
        for (int i = 0; i < 4; i++) {
            float4 o = make_float4(acc[i][0], acc[i][1], acc[i][2], acc[i][3]);
            *reinterpret_cast<float4*>(dst + (size_t)((ty << 2) + i) * N + cb + (tx << 2)) = o;
        }
        // final GBAR of the chunk loop already fenced smem reads/writes;
        // next tile's staging is safe immediately.
    }
}

// ---------------------------------------------------------------------------
// K-split reduce + bias + batch-BN (+ affine + ReLU). Remaining noise rides
// on extra CTAs (256 thr, 8 warps x JPW jobs each).
// ---------------------------------------------------------------------------
template <bool AR, int S, int RED, int JPW>
__global__ __launch_bounds__(256) void reduce_noise(const float* __restrict__ P,
                                                    const float* __restrict__ bias,
                                                    const float* __restrict__ gamma,
                                                    const float* __restrict__ beta,
                                                    float* __restrict__ Y, int N,
                                                    int jobBase)
{
    if (blockIdx.x >= RED) {
        const int b = (int)blockIdx.x - RED;
        const int wid = threadIdx.x >> 5;
        noise_jobs(jobBase + (b * 8 + wid) * JPW, JPW);
        return;
    }

    const int c = blockIdx.x * 256 + threadIdx.x;
    const float b = bias[c];
    float s = 0.f, ss = 0.f;
#pragma unroll 4
    for (int r = 0; r < 64; r++) {
        float v = b;
#pragma unroll
        for (int q = 0; q < S; q++) v += P[((size_t)q * 64 + r) * N + c];
        s += v; ss += v * v;
    }
    const float mean = s * 0.015625f;
    const float inv  = rsqrtf(fmaf(-mean, mean, ss * 0.015625f) + 1e-5f);
    const float ga = AR ? gamma[c] : 1.0f;
    const float be = AR ? beta[c]  : 0.0f;
#pragma unroll 4
    for (int r = 0; r < 64; r++) {
        float v = b;
#pragma unroll
        for (int q = 0; q < S; q++) v += P[((size_t)q * 64 + r) * N + c];
        float y = (v - mean) * inv;
        if (AR) y = fmaxf(fmaf(y, ga, be), 0.0f);
        Y[(size_t)r * N + c] = y;
    }
}

// ---------------------------------------------------------------------------
// Iteration kernel: pure (all noise complete). 64 CTAs, 256 thr, 8 cols/thr.
// Depth-3 software pipeline covers DRAM latency on the noise stream.
// ---------------------------------------------------------------------------
__device__ __forceinline__ float ex2f(float x)
{
    float y; asm("ex2.approx.f32 %0, %1;" : "=f"(y) : "f"(x)); return y;
}

__global__ __launch_bounds__(256) void iter_k(float* __restrict__ zout)
{
    const int row  = blockIdx.x;
    const int tid  = threadIdx.x;
    const int lane = tid & 31, wid = tid >> 5;
    const float C = 2.8853900817779268f;   // 2*log2(e)

    float4 ma = *(const float4*)(g_mask0 + row * 2048 + 8 * tid);
    float4 mb = *(const float4*)(g_mask0 + row * 2048 + 8 * tid + 4);
    float4 za = make_float4(0.f, 0.f, 0.f, 0.f);
    float4 zb = make_float4(0.f, 0.f, 0.f, 0.f);

    __shared__ __align__(16) float wsum[2][8];

    const float4* np = (const float4*)g_noise + (size_t)row * 512 + 2 * tid;

    float4 a0 = np[0],                   b0 = np[1];
    float4 a1 = np[(size_t)1 * 32768],   b1 = np[(size_t)1 * 32768 + 1];
    float4 a2 = np[(size_t)2 * 32768],   b2 = np[(size_t)2 * 32768 + 1];

    for (int i = 0; i < 1024; i++) {
        const float e0 = ex2f(fmaf(ma.x, C, a0.x));
        const float e1 = ex2f(fmaf(ma.y, C, a0.y));
        const float e2 = ex2f(fmaf(ma.z, C, a0.z));
        const float e3 = ex2f(fmaf(ma.w, C, a0.w));
        const float e4 = ex2f(fmaf(mb.x, C, b0.x));
        const float e5 = ex2f(fmaf(mb.y, C, b0.y));
        const float e6 = ex2f(fmaf(mb.z, C, b0.z));
        const float e7 = ex2f(fmaf(mb.w, C, b0.w));

        a0 = a1; b0 = b1;
        a1 = a2; b1 = b2;
        if (i + 3 < 1024) {
            a2 = np[(size_t)(i + 3) * 32768];
            b2 = np[(size_t)(i + 3) * 32768 + 1];
        }

        float s = ((e0 + e1) + (e2 + e3)) + ((e4 + e5) + (e6 + e7));
#pragma unroll
        for (int o = 16; o; o >>= 1) s += __shfl_xor_sync(0xffffffffu, s, o);
        if (lane == 0) wsum[i & 1][wid] = s;
        __syncthreads();

        const float4* wp = (const float4*)wsum[i & 1];
        const float4 t0 = wp[0], t1 = wp[1];
        const float tt = ((t0.x + t0.y) + (t0.z + t0.w)) + ((t1.x + t1.y) + (t1.z + t1.w));
        float r; asm("rcp.approx.f32 %0, %1;" : "=f"(r) : "f"(tt));
        ma.x = e0 * r; ma.y = e1 * r; ma.z = e2 * r; ma.w = e3 * r;
        mb.x = e4 * r; mb.y = e5 * r; mb.z = e6 * r; mb.w = e7 * r;
        za.x = fmaxf(za.x, ma.x); za.y = fmaxf(za.y, ma.y);
        za.z = fmaxf(za.z, ma.z); za.w = fmaxf(za.w, ma.w);
        zb.x = fmaxf(zb.x, mb.x); zb.y = fmaxf(zb.y, mb.y);
        zb.z = fmaxf(zb.z, mb.z); zb.w = fmaxf(zb.w, mb.w);
    }
    *(float4*)(zout + row * 2048 + 8 * tid)     = za;
    *(float4*)(zout + row * 2048 + 8 * tid + 4) = zb;
}

// ---------------------------------------------------------------------------
// Launch. Persistent hybrid grids (296 CTAs). Job budget 262144, duration-
// matched JPW in the gemm launches, remainder on reduces:
//   g1: 296 x 8 x 15 =  35520 @0        (512 tiles, Kc=512)
//   r1: 1024 x 8 x 4 =  32768 @35520
//   g2: 296 x 8 x 56 = 132608 @68288    (1024 tiles, Kc=1024)
//   r2: 512 x 8 x 4  =  16384 @200896
//   g3: 296 x 8 x 15 =  35520 @217280   (256 tiles, Kc=1024; 40 CTAs pure noise)
//   r3: 292 x 8 x 4  =   9344 @252800   (sum = 262144)
// ---------------------------------------------------------------------------
extern "C" void kernel_launch(void* const* d_in, const int* in_sizes, int n_in,
                              void* d_out, int out_size)
{
    const float* f   = (const float*)d_in[0];
    const float* W1  = (const float*)d_in[1];
    const float* b1  = (const float*)d_in[2];
    const float* g1  = (const float*)d_in[3];
    const float* be1 = (const float*)d_in[4];
    const float* W2  = (const float*)d_in[5];
    const float* b2  = (const float*)d_in[6];
    const float* g2  = (const float*)d_in[7];
    const float* be2 = (const float*)d_in[8];
    const float* W3  = (const float*)d_in[9];
    const float* b3  = (const float*)d_in[10];
    float* out = (float*)d_out;

    void *p1, *p2, *p3, *pp, *pp3;
    cudaGetSymbolAddress(&p1, g_h1);
    cudaGetSymbolAddress(&p2, g_h2);
    cudaGetSymbolAddress(&p3, g_mask0);
    cudaGetSymbolAddress(&pp, g_p);
    cudaGetSymbolAddress(&pp3, g_p3);
    float* h1 = (float*)p1;
    float* h2 = (float*)p2;
    float* mk = (float*)p3;
    float* P  = (float*)pp;
    float* P3 = (float*)pp3;

    keys_kernel<<<1, 1024>>>();

    gemm_noise<128, 4, 15><<<PGRID, 512>>>(f,  W1, P, 2048, 8192, 0);
    reduce_noise<true, 4, 32, 4><<<32 + 1024, 256>>>(P, b1, g1, be1, h1, 8192, 35520);

    gemm_noise<128, 8, 56><<<PGRID, 512>>>(h1, W2, P, 8192, 8192, 68288);
    reduce_noise<true, 8, 32, 4><<<32 + 512, 256>>>(P, b2, g2, be2, h2, 8192, 200896);

    gemm_noise<32, 8, 15><<<PGRID, 512>>>(h2, W3, P3, 8192, 2048, 217280);
    reduce_noise<false, 8, 8, 4><<<8 + 292, 256>>>(P3, b3, nullptr, nullptr, mk, 2048, 252800);

    iter_k<<<64, 256>>>(out);
}

// round 17
// speedup vs baseline: 1.1423x; 1.0334x over previous
#include <cuda_runtime.h>
#include <cuda_bf16.h>
#include <cstdint>
#include <cstddef>

// ---------------------------------------------------------------------------
// Scratch (device globals — no allocation allowed)
// ---------------------------------------------------------------------------
__device__ float g_noise[(size_t)1024 * 131072];   // 512 MiB prescaled gumbel noise
__device__ uint2 g_fhl [64 * 1024];                // f  packed hi/lo pairs [m][k/2]
__device__ uint2 g_h1hl[64 * 4096];                // h1 packed pairs
__device__ uint2 g_h2hl[64 * 4096];                // h2 packed pairs
__device__ float g_mask0[64 * 2048];
__device__ float g_p [(size_t)8 * 64 * 8192];      // K-split partials (g1 x4 / g2 x8)
__device__ float g_p3[(size_t)8 * 64 * 2048];      // gemm3 x8 partials
__device__ uint2 g_keys[1024];

#define PGRID 296   // persistent hybrid grid: 2 CTAs/SM x 148 SMs

// ---------------------------------------------------------------------------
// bf16 split helpers (R7-verified)
// ---------------------------------------------------------------------------
__device__ __forceinline__ uint32_t bfpack(float x0, float x1)
{
    __nv_bfloat162 h = __floats2bfloat162_rn(x0, x1);
    return reinterpret_cast<uint32_t&>(h);
}
__device__ __forceinline__ uint2 hilo_pair(float x0, float x1)
{
    __nv_bfloat16 h0 = __float2bfloat16(x0);
    __nv_bfloat16 h1 = __float2bfloat16(x1);
    float r0 = x0 - __bfloat162float(h0);
    float r1 = x1 - __bfloat162float(h1);
    uint2 o;
    o.x = ((uint32_t)reinterpret_cast<unsigned short&>(h1) << 16)
        | (uint32_t)reinterpret_cast<unsigned short&>(h0);
    o.y = bfpack(r0, r1);
    return o;
}

// mma.sync m16n8k16 row.col bf16 -> f32 (base sm_103 PTX; R7-verified layout)
__device__ __forceinline__ void mma16816(float* c, const uint32_t* a, const uint32_t* b)
{
    asm volatile("mma.sync.aligned.m16n8k16.row.col.f32.bf16.bf16.f32 "
                 "{%0,%1,%2,%3}, {%4,%5,%6,%7}, {%8,%9}, {%0,%1,%2,%3};"
                 : "+f"(c[0]), "+f"(c[1]), "+f"(c[2]), "+f"(c[3])
                 : "r"(a[0]), "r"(a[1]), "r"(a[2]), "r"(a[3]), "r"(b[0]), "r"(b[1]));
}

// ---------------------------------------------------------------------------
// Threefry-2x32-20 (bit-exact JAX)
// ---------------------------------------------------------------------------
__device__ __forceinline__ void tf_block(uint32_t ks0, uint32_t ks1, uint32_t ks2,
                                         uint32_t x0, uint32_t x1,
                                         uint32_t& o0, uint32_t& o1)
{
    x0 += ks0; x1 += ks1;
#define TFR(r) { x0 += x1; x1 = __funnelshift_l(x1, x1, (r)); x1 ^= x0; }
    TFR(13); TFR(15); TFR(26); TFR(6);
    x0 += ks1; x1 += ks2 + 1u;
    TFR(17); TFR(29); TFR(16); TFR(24);
    x0 += ks2; x1 += ks0 + 2u;
    TFR(13); TFR(15); TFR(26); TFR(6);
    x0 += ks0; x1 += ks1 + 3u;
    TFR(17); TFR(29); TFR(16); TFR(24);
    x0 += ks1; x1 += ks2 + 4u;
    TFR(13); TFR(15); TFR(26); TFR(6);
    x0 += ks2; x1 += ks0 + 5u;
#undef TFR
    o0 = x0; o1 = x1;
}

__global__ void keys_kernel()
{
    int i = threadIdx.x;
    uint32_t o0, o1;
    tf_block(0u, 42u, 0u ^ 42u ^ 0x1BD11BDAu, 0u, (uint32_t)i, o0, o1);
    g_keys[i] = make_uint2(o0, o1);
}

// convert f (64 x 2048 fp32) -> packed hi/lo pairs [64][1024]
__global__ __launch_bounds__(256) void prep_f(const float* __restrict__ f)
{
    int idx = blockIdx.x * 256 + threadIdx.x;     // 65536 total
    int m = idx >> 10, kp = idx & 1023;
    g_fhl[idx] = hilo_pair(f[m * 2048 + 2 * kp], f[m * 2048 + 2 * kp + 1]);
}

// bits -> n = -2*log2(-ln u)  so the iter loop is e = 2^(mask*C + n)
__device__ __forceinline__ float bits_to_noise(uint32_t bits)
{
    const uint32_t mant = bits >> 9;
    const float fl = __uint_as_float(0x3F800000u | mant) - 1.0f;  // exact m*2^-23
    float L;
    const float d = 1.0f - fl;
    if (d <= 0.015625f) {
        L = d * (1.0f + d * (0.5f + d * (0.3333333432674408f + d * 0.25f)));
    } else if (mant == 0u) {
        L = 87.336544750553109f;                                  // -ln(2^-126)
    } else {
        L = -0.69314718055994531f * __log2f(fl);
    }
    return -2.0f * __log2f(L);
}

// Noise warp-job: one warp generates 512 elements (16/thread). 262144 jobs.
__device__ __forceinline__ void noise_jobs(int jobBase, int njobs)
{
    const int lane = threadIdx.x & 31;
    for (int q = 0; q < njobs; q++) {
        const int g = jobBase + q;
        const int i = g >> 8;
        const int c = g & 255;
        const uint2 key = g_keys[i];
        const uint32_t k1 = key.x, k2 = key.y;
        const uint32_t ks2 = k1 ^ k2 ^ 0x1BD11BDAu;
        float* out = g_noise + (size_t)i * 131072u + (uint32_t)c * 512u + lane;
        const uint32_t j0 = (uint32_t)c * 512u + lane;
#pragma unroll 8
        for (int t = 0; t < 16; t++) {
            uint32_t o0, o1;
            tf_block(k1, k2, ks2, 0u, j0 + (uint32_t)t * 32u, o0, o1);
            out[t * 32] = bits_to_noise(o0 ^ o1);
        }
    }
}

// ---------------------------------------------------------------------------
// Hybrid persistent CTA: warps 0-7 noise, warps 8-15 gemm on the TENSOR pipe.
// Gemm: 64 x 64 tile, smem-staged split-bf16 HMMA, 4-pass hi/lo product,
// double-buffered 32-k chunks, one named barrier per chunk.
// A: packed uint2 [64][K/2] (hi,lo bf16x2). W: fp32, converted during staging.
// Writes raw fp32 partials P[kc][64][N].
// ---------------------------------------------------------------------------
#define GBAR() asm volatile("bar.sync 1, 256;" ::: "memory")

template <int COLTILES, int KSPLIT, int JPW>
__global__ __launch_bounds__(512, 2) void gemm_noise(const uint2* __restrict__ Ahl,
                                                     const float* __restrict__ W,
                                                     float* __restrict__ P,
                                                     int K, int N, int jobBase)
{
    constexpr int NTILES = COLTILES * KSPLIT;

    __shared__ __align__(16) uint2 As[2][64 * 18];   // [row][kpair], pad 18
    __shared__ __align__(16) uint2 Bs[2][16 * 66];   // [kpair][col], pad 66

    const int tid = threadIdx.x;
    const int wid = tid >> 5;

    if (wid < 8) {   // ---- noise role ----
        noise_jobs(jobBase + ((int)blockIdx.x * 8 + wid) * JPW, JPW);
        return;
    }

    // ---- gemm role ----
    const int t2   = tid - 256;
    const int lane = t2 & 31;
    const int gw   = wid - 8;              // 0..7
    const int mg   = gw & 1;               // M half (32 rows)
    const int ng   = gw >> 1;              // N quarter (16 cols)
    const int q    = lane & 3, l4 = lane >> 2;
    const int KP   = K >> 1;
    const int Kc   = K / KSPLIT;
    const int nch  = Kc >> 5;              // 32-k chunks per tile

    const int sa_row = t2 >> 2;            // A staging: row 0..63
    const int sa_kp4 = (t2 & 3) << 2;      //            kpair quad 0,4,8,12
    const int sb_kp  = t2 >> 4;            // B staging: kpair 0..15
    const int sb_n4  = (t2 & 15) << 2;     //            col quad

    for (int tile = (int)blockIdx.x; tile < NTILES; tile += PGRID) {
        const int col = tile % COLTILES;
        const int kc  = tile / COLTILES;
        const int cb  = col * 64;
        const int kp0 = kc * (Kc >> 1);
        const int k0g = kc * Kc;

        float acc[2][2][4] = {};

        // ---- stage chunk 0 ----
        uint4 av0, av1;
        float4 w0, w1;
        {
            const uint2* Ag = Ahl + (size_t)sa_row * KP + kp0 + sa_kp4;
            av0 = *(const uint4*)(Ag);
            av1 = *(const uint4*)(Ag + 2);
            const float* Wg = W + (size_t)(k0g + 2 * sb_kp) * N + cb + sb_n4;
            w0 = *(const float4*)(Wg);
            w1 = *(const float4*)(Wg + N);
        }
        {
            uint2* as = &As[0][sa_row * 18 + sa_kp4];
            *(uint4*)(as)     = av0;
            *(uint4*)(as + 2) = av1;
            uint2 p0 = hilo_pair(w0.x, w1.x), p1 = hilo_pair(w0.y, w1.y);
            uint2 p2 = hilo_pair(w0.z, w1.z), p3 = hilo_pair(w0.w, w1.w);
            uint2* bs = &Bs[0][sb_kp * 66 + sb_n4];
            *(uint4*)(bs)     = make_uint4(p0.x, p0.y, p1.x, p1.y);
            *(uint4*)(bs + 2) = make_uint4(p2.x, p2.y, p3.x, p3.y);
        }
        GBAR();

        int buf = 0;
        for (int ch = 0; ch < nch; ch++) {
            const bool more = (ch + 1 < nch);
            if (more) {   // prefetch chunk ch+1 into registers
                const uint2* Ag = Ahl + (size_t)sa_row * KP + kp0 + (ch + 1) * 16 + sa_kp4;
                av0 = *(const uint4*)(Ag);
                av1 = *(const uint4*)(Ag + 2);
                const float* Wg = W + (size_t)(k0g + (ch + 1) * 32 + 2 * sb_kp) * N + cb + sb_n4;
                w0 = *(const float4*)(Wg);
                w1 = *(const float4*)(Wg + N);
            }

            // ---- compute: two k16 steps on buf ----
#pragma unroll
            for (int s = 0; s < 2; s++) {
                const int kpb = s * 8;
                uint32_t ah[2][4], al[2][4], bh[2][2], bl[2][2];
#pragma unroll
                for (int mf = 0; mf < 2; mf++) {
                    const int rb = mg * 32 + mf * 16 + l4;
                    const uint2 A0 = As[buf][(rb)     * 18 + kpb + q];
                    const uint2 A1 = As[buf][(rb + 8) * 18 + kpb + q];
                    const uint2 A2 = As[buf][(rb)     * 18 + kpb + q + 4];
                    const uint2 A3 = As[buf][(rb + 8) * 18 + kpb + q + 4];
                    ah[mf][0] = A0.x; ah[mf][1] = A1.x; ah[mf][2] = A2.x; ah[mf][3] = A3.x;
                    al[mf][0] = A0.y; al[mf][1] = A1.y; al[mf][2] = A2.y; al[mf][3] = A3.y;
                }
#pragma unroll
                for (int nf = 0; nf < 2; nf++) {
                    const int cc = ng * 16 + nf * 8 + l4;
                    const uint2 B0 = Bs[buf][(kpb + q)     * 66 + cc];
                    const uint2 B1 = Bs[buf][(kpb + q + 4) * 66 + cc];
                    bh[nf][0] = B0.x; bh[nf][1] = B1.x;
                    bl[nf][0] = B0.y; bl[nf][1] = B1.y;
                }
#pragma unroll
                for (int mf = 0; mf < 2; mf++)
#pragma unroll
                    for (int nf = 0; nf < 2; nf++) {
                        mma16816(acc[mf][nf], ah[mf], bh[nf]);
                        mma16816(acc[mf][nf], ah[mf], bl[nf]);
                        mma16816(acc[mf][nf], al[mf], bh[nf]);
                        mma16816(acc[mf][nf], al[mf], bl[nf]);
                    }
            }

            if (more) {   // store chunk ch+1 into buf^1 (not being read)
                const int nb = buf ^ 1;
                uint2* as = &As[nb][sa_row * 18 + sa_kp4];
                *(uint4*)(as)     = av0;
                *(uint4*)(as + 2) = av1;
                uint2 p0 = hilo_pair(w0.x, w1.x), p1 = hilo_pair(w0.y, w1.y);
                uint2 p2 = hilo_pair(w0.z, w1.z), p3 = hilo_pair(w0.w, w1.w);
                uint2* bs = &Bs[nb][sb_kp * 66 + sb_n4];
                *(uint4*)(bs)     = make_uint4(p0.x, p0.y, p1.x, p1.y);
                *(uint4*)(bs + 2) = make_uint4(p2.x, p2.y, p3.x, p3.y);
            }
            GBAR();       // compute(buf) done AND sts(buf^1) visible
            buf ^= 1;
        }

        // ---- epilogue: fp32 partials ----
        float* dst = P + (size_t)kc * 64 * N;
#pragma unroll
        for (int mf = 0; mf < 2; mf++) {
            const int r = mg * 32 + mf * 16 + l4;
#pragma unroll
            for (int nf = 0; nf < 2; nf++) {
                const int cc = cb + ng * 16 + nf * 8 + 2 * q;
                *(float2*)(dst + (size_t)r * N + cc)       = make_float2(acc[mf][nf][0], acc[mf][nf][1]);
                *(float2*)(dst + (size_t)(r + 8) * N + cc) = make_float2(acc[mf][nf][2], acc[mf][nf][3]);
            }
        }
    }
}

// ---------------------------------------------------------------------------
// K-split reduce + bias + batch-BN (+ affine + ReLU). 2 cols/thread.
// AR=true -> emit packed hi/lo pairs (next GEMM's A). Extra CTAs = noise.
// ---------------------------------------------------------------------------
template <bool AR, int S, int RED, int JPW>
__global__ __launch_bounds__(256) void reduce_noise(const float* __restrict__ P,
                                                    const float* __restrict__ bias,
                                                    const float* __restrict__ gamma,
                                                    const float* __restrict__ beta,
                                                    uint2* __restrict__ AhlOut,
                                                    float* __restrict__ Yout,
                                                    int N, int jobBase)
{
    if (blockIdx.x >= RED) {
        const int b = (int)blockIdx.x - RED;
        const int wid = threadIdx.x >> 5;
        noise_jobs(jobBase + (b * 8 + wid) * JPW, JPW);
        return;
    }

    const int cp = blockIdx.x * 256 + threadIdx.x;   // column-pair index
    const int c0 = cp * 2;
    const float b0 = bias[c0], b1 = bias[c0 + 1];
    float s0 = 0.f, ss0 = 0.f, s1 = 0.f, ss1 = 0.f;
#pragma unroll 4
    for (int r = 0; r < 64; r++) {
        float v0 = b0, v1 = b1;
#pragma unroll
        for (int qq = 0; qq < S; qq++) {
            float2 v = *(const float2*)(P + ((size_t)qq * 64 + r) * N + c0);
            v0 += v.x; v1 += v.y;
        }
        s0 += v0; ss0 += v0 * v0;
        s1 += v1; ss1 += v1 * v1;
    }
    const float m0 = s0 * 0.015625f, m1 = s1 * 0.015625f;
    const float i0 = rsqrtf(fmaf(-m0, m0, ss0 * 0.015625f) + 1e-5f);
    const float i1 = rsqrtf(fmaf(-m1, m1, ss1 * 0.015625f) + 1e-5f);
    const float ga0 = AR ? gamma[c0] : 1.0f, ga1 = AR ? gamma[c0 + 1] : 1.0f;
    const float be0 = AR ? beta[c0]  : 0.0f, be1 = AR ? beta[c0 + 1]  : 0.0f;
#pragma unroll 4
    for (int r = 0; r < 64; r++) {
        float v0 = b0, v1 = b1;
#pragma unroll
        for (int qq = 0; qq < S; qq++) {
            float2 v = *(const float2*)(P + ((size_t)qq * 64 + r) * N + c0);
            v0 += v.x; v1 += v.y;
        }
        float y0 = (v0 - m0) * i0;
        float y1 = (v1 - m1) * i1;
        if (AR) {
            y0 = fmaxf(fmaf(y0, ga0, be0), 0.0f);
            y1 = fmaxf(fmaf(y1, ga1, be1), 0.0f);
            AhlOut[(size_t)r * (N >> 1) + cp] = hilo_pair(y0, y1);
        } else {
            *(float2*)(Yout + (size_t)r * N + c0) = make_float2(y0, y1);
        }
    }
}

// ---------------------------------------------------------------------------
// Iteration kernel: pure. 64 CTAs, 256 thr, 8 cols/thread, depth-3 pipeline.
// ---------------------------------------------------------------------------
__device__ __forceinline__ float ex2f(float x)
{
    float y; asm("ex2.approx.f32 %0, %1;" : "=f"(y) : "f"(x)); return y;
}

__global__ __launch_bounds__(256) void iter_k(float* __restrict__ zout)
{
    const int row  = blockIdx.x;
    const int tid  = threadIdx.x;
    const int lane = tid & 31, wid = tid >> 5;
    const float C = 2.8853900817779268f;   // 2*log2(e)

    float4 ma = *(const float4*)(g_mask0 + row * 2048 + 8 * tid);
    float4 mb = *(const float4*)(g_mask0 + row * 2048 + 8 * tid + 4);
    float4 za = make_float4(0.f, 0.f, 0.f, 0.f);
    float4 zb = make_float4(0.f, 0.f, 0.f, 0.f);

    __shared__ __align__(16) float wsum[2][8];

    const float4* np = (const float4*)g_noise + (size_t)row * 512 + 2 * tid;

    float4 a0 = np[0],                 b0 = np[1];
    float4 a1 = np[(size_t)1 * 32768], b1 = np[(size_t)1 * 32768 + 1];
    float4 a2 = np[(size_t)2 * 32768], b2 = np[(size_t)2 * 32768 + 1];

    for (int i = 0; i < 1024; i++) {
        const float e0 = ex2f(fmaf(ma.x, C, a0.x));
        const float e1 = ex2f(fmaf(ma.y, C, a0.y));
        const float e2 = ex2f(fmaf(ma.z, C, a0.z));
        const float e3 = ex2f(fmaf(ma.w, C, a0.w));
        const float e4 = ex2f(fmaf(mb.x, C, b0.x));
        const float e5 = ex2f(fmaf(mb.y, C, b0.y));
        const float e6 = ex2f(fmaf(mb.z, C, b0.z));
        const float e7 = ex2f(fmaf(mb.w, C, b0.w));

        a0 = a1; b0 = b1;
        a1 = a2; b1 = b2;
        if (i + 3 < 1024) {
            a2 = np[(size_t)(i + 3) * 32768];
            b2 = np[(size_t)(i + 3) * 32768 + 1];
        }

        float s = ((e0 + e1) + (e2 + e3)) + ((e4 + e5) + (e6 + e7));
#pragma unroll
        for (int o = 16; o; o >>= 1) s += __shfl_xor_sync(0xffffffffu, s, o);
        if (lane == 0) wsum[i & 1][wid] = s;
        __syncthreads();

        const float4* wp = (const float4*)wsum[i & 1];
        const float4 t0 = wp[0], t1 = wp[1];
        const float tt = ((t0.x + t0.y) + (t0.z + t0.w)) + ((t1.x + t1.y) + (t1.z + t1.w));
        float r; asm("rcp.approx.f32 %0, %1;" : "=f"(r) : "f"(tt));
        ma.x = e0 * r; ma.y = e1 * r; ma.z = e2 * r; ma.w = e3 * r;
        mb.x = e4 * r; mb.y = e5 * r; mb.z = e6 * r; mb.w = e7 * r;
        za.x = fmaxf(za.x, ma.x); za.y = fmaxf(za.y, ma.y);
        za.z = fmaxf(za.z, ma.z); za.w = fmaxf(za.w, ma.w);
        zb.x = fmaxf(zb.x, mb.x); zb.y = fmaxf(zb.y, mb.y);
        zb.z = fmaxf(zb.z, mb.z); zb.w = fmaxf(zb.w, mb.w);
    }
    *(float4*)(zout + row * 2048 + 8 * tid)     = za;
    *(float4*)(zout + row * 2048 + 8 * tid + 4) = zb;
}

// ---------------------------------------------------------------------------
// Launch. 262144 noise warp-jobs, iteration-ordered:
//   g1: 296x8x14 = 33152 @0          r1: 512x8x8 = 32768 @33152
//   g2: 296x8x48 = 113664 @65920     r2: 256x8x8 = 16384 @179584
//   g3: 296x8x14 = 33152 @195968     r3: 516x8x8 = 33024 @229120
// ---------------------------------------------------------------------------
extern "C" void kernel_launch(void* const* d_in, const int* in_sizes, int n_in,
                              void* d_out, int out_size)
{
    const float* f   = (const float*)d_in[0];
    const float* W1  = (const float*)d_in[1];
    const float* b1  = (const float*)d_in[2];
    const float* g1  = (const float*)d_in[3];
    const float* be1 = (const float*)d_in[4];
    const float* W2  = (const float*)d_in[5];
    const float* b2  = (const float*)d_in[6];
    const float* g2  = (const float*)d_in[7];
    const float* be2 = (const float*)d_in[8];
    const float* W3  = (const float*)d_in[9];
    const float* b3  = (const float*)d_in[10];
    float* out = (float*)d_out;

    void *pf, *p1, *p2, *p3, *pp, *pp3;
    cudaGetSymbolAddress(&pf, g_fhl);
    cudaGetSymbolAddress(&p1, g_h1hl);
    cudaGetSymbolAddress(&p2, g_h2hl);
    cudaGetSymbolAddress(&p3, g_mask0);
    cudaGetSymbolAddress(&pp, g_p);
    cudaGetSymbolAddress(&pp3, g_p3);
    uint2* fhl  = (uint2*)pf;
    uint2* h1hl = (uint2*)p1;
    uint2* h2hl = (uint2*)p2;
    float* mk   = (float*)p3;
    float* P    = (float*)pp;
    float* P3   = (float*)pp3;

    keys_kernel<<<1, 1024>>>();
    prep_f<<<256, 256>>>(f);

    gemm_noise<128, 4, 14><<<PGRID, 512>>>(fhl, W1, P, 2048, 8192, 0);
    reduce_noise<true, 4, 16, 8><<<16 + 512, 256>>>(P, b1, g1, be1, h1hl, nullptr, 8192, 33152);

    gemm_noise<128, 8, 48><<<PGRID, 512>>>(h1hl, W2, P, 8192, 8192, 65920);
    reduce_noise<true, 8, 16, 8><<<16 + 256, 256>>>(P, b2, g2, be2, h2hl, nullptr, 8192, 179584);

    gemm_noise<32, 8, 14><<<PGRID, 512>>>(h2hl, W3, P3, 8192, 2048, 195968);
    reduce_noise<false, 8, 4, 8><<<4 + 516, 256>>>(P3, b3, nullptr, nullptr, nullptr, mk, 2048, 229120);

    iter_k<<<64, 256>>>(out);
}